// round 12
// baseline (speedup 1.0000x reference)
#include <cuda_runtime.h>
#include <cuda_bf16.h>
#include <cstdint>

// Problem constants
#define N_ROWS 16384
#define D_IN   1024
#define D_OUT  512
#define N_EXP  8
#define NPAD   (N_ROWS + N_EXP * 128)   // 17408: per-expert 128-padded row space

// GEMM tiling
#define BM 128
#define BN 128
#define KC 32
#define NCHUNK (D_IN / KC)              // 32
#define NSTAGE 4
#define NTHREADS 512
#define MAX_TILES (N_ROWS / BM + N_EXP) // 136
#define NSM 148

// SMEM stage: X0 | X1 | W0 | W1, each 128 rows x 32B = 4KB -> 16KB/stage
#define STG 16384
#define SMEM_TOTAL (NSTAGE * STG)       // 65536

// ---------------- device scratch ------------------------------------------
__device__ int g_cnt[N_EXP];
__device__ int g_cur[N_EXP];
__device__ int g_off[N_EXP + 1];
__device__ int g_end[N_EXP];
__device__ int g_perm[NPAD];
__device__ int g_tile_e[MAX_TILES];
__device__ int g_tile_r[MAX_TILES];
__device__ int g_work;                  // persistent-GEMM work counter
__device__ int g_nwork;                 // total work items = ntiles * 4
__device__ uint8_t g_x0c[(size_t)NCHUNK * NPAD * 32];
__device__ uint8_t g_x1c[(size_t)NCHUNK * NPAD * 32];
__device__ uint8_t g_w0c[(size_t)N_EXP * NCHUNK * D_OUT * 32];
__device__ uint8_t g_w1c[(size_t)N_EXP * NCHUNK * D_OUT * 32];
__device__ float   g_invqx[NPAD];
__device__ float   g_invqw[N_EXP * D_OUT];

// ---------------- PTX helpers ----------------------------------------------
__device__ __forceinline__ uint32_t smem_u32(const void* p) {
    uint32_t a;
    asm("{ .reg .u64 t; cvta.to.shared.u64 t, %1; cvt.u32.u64 %0, t; }" : "=r"(a) : "l"(p));
    return a;
}
#define MBARRIER_INIT(a, n) \
    asm volatile("mbarrier.init.shared.b64 [%0], %1;" :: "r"((uint32_t)(a)), "r"((uint32_t)(n)) : "memory")
#define MBARRIER_EXPECT_TX(a, tx) \
    asm volatile("mbarrier.arrive.expect_tx.shared.b64 _, [%0], %1;" :: "r"((uint32_t)(a)), "r"((uint32_t)(tx)) : "memory")
#define MBARRIER_WAIT_PARITY(a, ph) do { \
    uint32_t _m = (uint32_t)(a); uint32_t _p = (uint32_t)(ph); uint32_t _d; \
    asm volatile("{ .reg .pred p; mbarrier.try_wait.parity.acquire.cta.shared::cta.b64 p, [%1], %2; selp.b32 %0, 1, 0, p; }" \
        : "=r"(_d) : "r"(_m), "r"(_p) : "memory"); \
    if (!_d) { \
        asm volatile("{ .reg .pred P1; WL_%=: mbarrier.try_wait.parity.acquire.cta.shared::cta.b64 P1, [%0], %1, 0x989680; @P1 bra.uni WD_%=; bra.uni WL_%=; WD_%=: }" \
            :: "r"(_m), "r"(_p) : "memory"); \
    } } while (0)
__device__ __forceinline__ void bulk_g2s(uint32_t dst, const void* src, uint32_t bytes, uint32_t mbar) {
    asm volatile("cp.async.bulk.shared::cluster.global.mbarrier::complete_tx::bytes [%0], [%1], %2, [%3];"
                 :: "r"(dst), "l"(src), "r"(bytes), "r"(mbar) : "memory");
}
__device__ __forceinline__ void ldsm4(uint32_t* r, uint32_t a) {
    asm volatile("ldmatrix.sync.aligned.m8n8.x4.shared.b16 {%0,%1,%2,%3}, [%4];"
                 : "=r"(r[0]), "=r"(r[1]), "=r"(r[2]), "=r"(r[3]) : "r"(a));
}
__device__ __forceinline__ void mma_s8(int* c, const uint32_t* a, uint32_t b0, uint32_t b1) {
    asm volatile("mma.sync.aligned.m16n8k32.row.col.s32.s8.s8.s32 "
                 "{%0,%1,%2,%3}, {%4,%5,%6,%7}, {%8,%9}, {%0,%1,%2,%3};"
                 : "+r"(c[0]), "+r"(c[1]), "+r"(c[2]), "+r"(c[3])
                 : "r"(a[0]), "r"(a[1]), "r"(a[2]), "r"(a[3]), "r"(b0), "r"(b1));
}

// ---------------- bucketing -------------------------------------------------
// single block, 1024 threads: histogram in registers, also zeroes g_cur
__global__ void k_hist1(const int* __restrict__ idx) {
    const int t = threadIdx.x;
    int cnt[N_EXP];
    #pragma unroll
    for (int k = 0; k < N_EXP; ++k) cnt[k] = 0;
    for (int i = t; i < N_ROWS; i += 1024) {
        const int e = idx[i];
        #pragma unroll
        for (int k = 0; k < N_EXP; ++k) cnt[k] += (e == k);
    }
    #pragma unroll
    for (int k = 0; k < N_EXP; ++k)
        #pragma unroll
        for (int o = 16; o > 0; o >>= 1)
            cnt[k] += __shfl_xor_sync(0xffffffffu, cnt[k], o);
    __shared__ int acc[N_EXP];
    if (t < N_EXP) acc[t] = 0;
    __syncthreads();
    if ((t & 31) == 0)
        #pragma unroll
        for (int k = 0; k < N_EXP; ++k) atomicAdd(&acc[k], cnt[k]);
    __syncthreads();
    if (t < N_EXP) { g_cnt[t] = acc[t]; g_cur[t] = 0; }
}
__global__ void k_scan() {
    int off = 0, t = 0;
    for (int e = 0; e < N_EXP; ++e) {
        g_off[e] = off;
        int c = g_cnt[e];
        for (int r = 0; r < c; r += BM) { g_tile_e[t] = e; g_tile_r[t] = off + r; ++t; }
        g_end[e] = off + c;
        off += (c + BM - 1) & ~(BM - 1);
    }
    g_off[N_EXP] = off;
    g_work = 0;
    g_nwork = t * (D_OUT / BN);
}
// smem-aggregated scatter: one global atomicAdd per expert per block
__global__ void k_scatter(const int* __restrict__ idx) {
    __shared__ int loc[N_EXP], base[N_EXP];
    const int tid = threadIdx.x;
    if (tid < N_EXP) loc[tid] = 0;
    __syncthreads();
    const int i = blockIdx.x * 256 + tid;       // 64 * 256 == N_ROWS exactly
    const int e = idx[i];
    const int r = atomicAdd(&loc[e], 1);
    __syncthreads();
    if (tid < N_EXP) base[tid] = atomicAdd(&g_cur[tid], loc[tid]);
    __syncthreads();
    g_perm[g_off[e] + base[e] + r] = i;
}

// ---------------- fused int8 two-stream quantization ------------------------
__device__ __forceinline__ float rowmax256(float4 v) {
    __shared__ float red[8];
    const int t = threadIdx.x;
    float m = fmaxf(fmaxf(fabsf(v.x), fabsf(v.y)), fmaxf(fabsf(v.z), fabsf(v.w)));
    #pragma unroll
    for (int o = 16; o > 0; o >>= 1) m = fmaxf(m, __shfl_xor_sync(0xffffffffu, m, o));
    if ((t & 31) == 0) red[t >> 5] = m;
    __syncthreads();
    if (t < 32) {
        float mm = (t < 8) ? red[t] : 0.f;
        #pragma unroll
        for (int o = 4; o > 0; o >>= 1) mm = fmaxf(mm, __shfl_xor_sync(0xffffffffu, mm, o));
        if (t == 0) red[0] = fmaxf(mm, 1e-30f);
    }
    __syncthreads();
    return red[0];
}
__device__ __forceinline__ void quant4(float4 v, float q, uchar4& c0, uchar4& c1) {
    uint8_t* p0 = (uint8_t*)&c0; uint8_t* p1 = (uint8_t*)&c1;
    float f[4] = {v.x, v.y, v.z, v.w};
    #pragma unroll
    for (int i = 0; i < 4; ++i) {
        float fq = f[i] * q;
        float x0 = rintf(fq);
        x0 = fminf(127.f, fmaxf(-127.f, x0));
        float x1 = rintf((fq - x0) * 128.f);
        x1 = fminf(127.f, fmaxf(-127.f, x1));
        p0[i] = (uint8_t)(int8_t)(int)x0;
        p1[i] = (uint8_t)(int8_t)(int)x1;
    }
}
// blocks [0, E*D_OUT): W rows; blocks [E*D_OUT, E*D_OUT+NPAD): x slots
__global__ void k_convert(const float* __restrict__ x, const float* __restrict__ W) {
    const int bb = blockIdx.x;
    const int t = threadIdx.x;
    if (bb < N_EXP * D_OUT) {
        const int r = bb;
        const int e = r >> 9, co = r & 511;
        float4 v = ((const float4*)(W + (size_t)r * D_IN))[t];
        const float maxv = rowmax256(v);
        uchar4 c0, c1;
        quant4(v, 127.f / maxv, c0, c1);
        const int ck = t >> 3;
        const int j  = (t & 7) * 4;
        const int js = j ^ ((co & 4) ? 16 : 0);
        const size_t base = ((size_t)(e * NCHUNK + ck) * D_OUT + co) * 32 + js;
        *(uchar4*)(g_w0c + base) = c0;
        *(uchar4*)(g_w1c + base) = c1;
        if (t == 0) g_invqw[r] = maxv * (1.f / 127.f);
    } else {
        const int p = bb - N_EXP * D_OUT;
        int e = 0;
        #pragma unroll
        for (int k = 1; k < N_EXP; ++k) e += (p >= g_off[k]);
        if (p >= g_end[e]) return;                 // pad slot: skip
        const int src = g_perm[p];
        float4 v = ((const float4*)(x + (size_t)src * D_IN))[t];
        const float maxv = rowmax256(v);
        uchar4 c0, c1;
        quant4(v, 127.f / maxv, c0, c1);
        const int ck = t >> 3;
        const int j  = (t & 7) * 4;
        const int js = j ^ ((p & 4) ? 16 : 0);
        const size_t base = ((size_t)ck * NPAD + p) * 32 + js;
        *(uchar4*)(g_x0c + base) = c0;
        *(uchar4*)(g_x1c + base) = c1;
        if (t == 0) g_invqx[p] = maxv * (1.f / 127.f);
    }
}

// ---------------- persistent grouped int8 GEMM ------------------------------
__device__ __forceinline__ void issue_chunk(uint32_t sb, uint32_t mb, int stage,
                                            int ck, int row0, int e, int n0) {
    MBARRIER_EXPECT_TX(mb, STG);
    const uint32_t st = sb + stage * STG;
    bulk_g2s(st,         g_x0c + ((size_t)ck * NPAD + row0) * 32, 4096, mb);
    bulk_g2s(st + 4096,  g_x1c + ((size_t)ck * NPAD + row0) * 32, 4096, mb);
    bulk_g2s(st + 8192,  g_w0c + ((size_t)(e * NCHUNK + ck) * D_OUT + n0) * 32, 4096, mb);
    bulk_g2s(st + 12288, g_w1c + ((size_t)(e * NCHUNK + ck) * D_OUT + n0) * 32, 4096, mb);
}

__global__ void __launch_bounds__(NTHREADS, 1) k_gemm(const float* __restrict__ b,
                                                      float* __restrict__ y) {
    extern __shared__ char smem[];
    __shared__ uint64_t mbar[NSTAGE];
    __shared__ int s_wk;
    const uint32_t sb = smem_u32(smem);

    const int tid  = threadIdx.x;
    const int lane = tid & 31;
    const int warp = tid >> 5;
    const int warp_m = warp >> 2;
    const int warp_n = warp & 3;

    if (tid == 0) {
        #pragma unroll
        for (int s = 0; s < NSTAGE; ++s) MBARRIER_INIT(smem_u32(&mbar[s]), 1);
    }
    __syncthreads();

    const uint32_t a_row  = warp_m * 32 + (lane & 15);
    const uint32_t a_koff = (lane >> 4) * 16;
    const uint32_t aswz   = (a_row & 4) ? 16u : 0u;
    const uint32_t b_row  = warp_n * 32 + (lane & 7) + ((lane >> 4) & 1) * 8;
    const uint32_t b_koff = ((lane >> 3) & 1) * 16;
    const uint32_t bswz   = (b_row & 4) ? 16u : 0u;

    int gi = 0, gc = 0;      // global chunk issue/consume counters (parity source)
    const int nwork = g_nwork;

    for (;;) {
        if (tid == 0) s_wk = atomicAdd(&g_work, 1);
        __syncthreads();
        const int wk = s_wk;
        if (wk >= nwork) break;
        const int tl = wk >> 2;
        const int e     = g_tile_e[tl];
        const int row0  = g_tile_r[tl];
        const int row_end = g_end[e];
        const int n0    = (wk & 3) * BN;

        if (tid == 0) {
            #pragma unroll
            for (int k = 0; k < 3; ++k) {
                issue_chunk(sb, smem_u32(&mbar[(gi & 3)]), gi & 3, k, row0, e, n0);
                ++gi;
            }
        }

        int accA[2][4][4], accC[2][4][4];
        #pragma unroll
        for (int i = 0; i < 2; ++i)
            #pragma unroll
            for (int j = 0; j < 4; ++j)
                #pragma unroll
                for (int k = 0; k < 4; ++k) { accA[i][j][k] = 0; accC[i][j][k] = 0; }

        for (int c = 0; c < NCHUNK; ++c) {
            const int s = gc & 3;
            MBARRIER_WAIT_PARITY(smem_u32(&mbar[s]), (gc >> 2) & 1);
            __syncthreads();
            if (tid == 0 && c + 3 < NCHUNK) {
                issue_chunk(sb, smem_u32(&mbar[(gi & 3)]), gi & 3, c + 3, row0, e, n0);
                ++gi;
            }

            const uint32_t st = sb + s * STG;
            uint32_t a0[2][4], a1[2][4], w0[2][4], w1[2][4];
            #pragma unroll
            for (int mt = 0; mt < 2; ++mt) {
                const uint32_t ad = st + (a_row + mt * 16) * 32 + (a_koff ^ aswz);
                ldsm4(a0[mt], ad);
                ldsm4(a1[mt], ad + 4096);
            }
            #pragma unroll
            for (int nt2 = 0; nt2 < 2; ++nt2) {
                const uint32_t bd = st + 8192 + (b_row + nt2 * 16) * 32 + (b_koff ^ bswz);
                ldsm4(w0[nt2], bd);
                ldsm4(w1[nt2], bd + 4096);
            }
            #pragma unroll
            for (int mt = 0; mt < 2; ++mt)
                #pragma unroll
                for (int nt = 0; nt < 4; ++nt) {
                    const uint32_t* p0 = &w0[nt >> 1][(nt & 1) * 2];
                    const uint32_t* p1 = &w1[nt >> 1][(nt & 1) * 2];
                    mma_s8(accA[mt][nt], a0[mt], p0[0], p0[1]);
                    mma_s8(accC[mt][nt], a0[mt], p1[0], p1[1]);
                    mma_s8(accC[mt][nt], a1[mt], p0[0], p0[1]);
                }
            ++gc;
        }

        // epilogue
        const float inv128 = 1.f / 128.f;
        const int ncol = n0 + warp_n * 32 + (lane & 3) * 2;
        float2 bias[4], fw[4];
        #pragma unroll
        for (int nt = 0; nt < 4; ++nt) {
            bias[nt] = *(const float2*)(b + (size_t)e * D_OUT + ncol + nt * 8);
            fw[nt]   = *(const float2*)(g_invqw + (size_t)e * D_OUT + ncol + nt * 8);
        }
        #pragma unroll
        for (int mt = 0; mt < 2; ++mt)
            #pragma unroll
            for (int half = 0; half < 2; ++half) {
                const int sr = row0 + warp_m * 32 + mt * 16 + (lane >> 2) + half * 8;
                if (sr < row_end) {
                    const int g = g_perm[sr];
                    const float fx = g_invqx[sr];
                    float* yp = y + (size_t)g * D_OUT + ncol;
                    #pragma unroll
                    for (int nt = 0; nt < 4; ++nt) {
                        float v0 = (float)accA[mt][nt][half * 2 + 0]
                                 + (float)accC[mt][nt][half * 2 + 0] * inv128;
                        float v1 = (float)accA[mt][nt][half * 2 + 1]
                                 + (float)accC[mt][nt][half * 2 + 1] * inv128;
                        float2 v;
                        v.x = v0 * fx * fw[nt].x + bias[nt].x;
                        v.y = v1 * fx * fw[nt].y + bias[nt].y;
                        *(float2*)(yp + nt * 8) = v;
                    }
                }
            }
        __syncthreads();   // all stage reads done before next tile's prime
    }
}

// ---------------- entry -----------------------------------------------------
extern "C" void kernel_launch(void* const* d_in, const int* in_sizes, int n_in,
                              void* d_out, int out_size) {
    const float* x   = (const float*)d_in[0];
    const int*   idx = (const int*)  d_in[1];
    const float* W   = (const float*)d_in[2];
    const float* b   = (const float*)d_in[3];
    float*       y   = (float*)d_out;

    cudaFuncSetAttribute(k_gemm, cudaFuncAttributeMaxDynamicSharedMemorySize, SMEM_TOTAL);

    k_hist1<<<1, 1024>>>(idx);
    k_scan<<<1, 1>>>();
    k_scatter<<<N_ROWS / 256, 256>>>(idx);
    k_convert<<<N_EXP * D_OUT + NPAD, 256>>>(x, W);
    k_gemm<<<NSM, NTHREADS, SMEM_TOTAL>>>(b, y);
}

// round 13
// speedup vs baseline: 1.0163x; 1.0163x over previous
#include <cuda_runtime.h>
#include <cuda_bf16.h>
#include <cstdint>

// Problem constants
#define N_ROWS 16384
#define D_IN   1024
#define D_OUT  512
#define N_EXP  8
#define NPAD   (N_ROWS + N_EXP * 128)   // 17408: per-expert 128-padded row space

// GEMM tiling
#define BM 128
#define BN 128
#define KC 32
#define NCHUNK (D_IN / KC)              // 32
#define NSTAGE 4
#define NTHREADS 512
#define MAX_TILES (N_ROWS / BM + N_EXP) // 136

// SMEM stage: X0 | X1 | W0 | W1, each 128 rows x 32B = 4KB -> 16KB/stage
#define STG 16384
#define SMEM_TOTAL (NSTAGE * STG)       // 65536

// ---------------- device scratch ------------------------------------------
__device__ int g_cur[N_EXP];
__device__ int g_off[N_EXP + 1];
__device__ int g_end[N_EXP];
__device__ int g_perm[NPAD];
__device__ int g_tile_e[MAX_TILES];
__device__ int g_tile_r[MAX_TILES];
__device__ uint8_t g_x0c[(size_t)NCHUNK * NPAD * 32];
__device__ uint8_t g_x1c[(size_t)NCHUNK * NPAD * 32];
__device__ uint8_t g_w0c[(size_t)N_EXP * NCHUNK * D_OUT * 32];
__device__ uint8_t g_w1c[(size_t)N_EXP * NCHUNK * D_OUT * 32];
__device__ float   g_invqx[NPAD];
__device__ float   g_invqw[N_EXP * D_OUT];

// ---------------- PTX helpers ----------------------------------------------
__device__ __forceinline__ uint32_t smem_u32(const void* p) {
    uint32_t a;
    asm("{ .reg .u64 t; cvta.to.shared.u64 t, %1; cvt.u32.u64 %0, t; }" : "=r"(a) : "l"(p));
    return a;
}
#define MBARRIER_INIT(a, n) \
    asm volatile("mbarrier.init.shared.b64 [%0], %1;" :: "r"((uint32_t)(a)), "r"((uint32_t)(n)) : "memory")
#define MBARRIER_EXPECT_TX(a, tx) \
    asm volatile("mbarrier.arrive.expect_tx.shared.b64 _, [%0], %1;" :: "r"((uint32_t)(a)), "r"((uint32_t)(tx)) : "memory")
#define MBARRIER_WAIT_PARITY(a, ph) do { \
    uint32_t _m = (uint32_t)(a); uint32_t _p = (uint32_t)(ph); uint32_t _d; \
    asm volatile("{ .reg .pred p; mbarrier.try_wait.parity.acquire.cta.shared::cta.b64 p, [%1], %2; selp.b32 %0, 1, 0, p; }" \
        : "=r"(_d) : "r"(_m), "r"(_p) : "memory"); \
    if (!_d) { \
        asm volatile("{ .reg .pred P1; WL_%=: mbarrier.try_wait.parity.acquire.cta.shared::cta.b64 P1, [%0], %1, 0x989680; @P1 bra.uni WD_%=; bra.uni WL_%=; WD_%=: }" \
            :: "r"(_m), "r"(_p) : "memory"); \
    } } while (0)
__device__ __forceinline__ void bulk_g2s(uint32_t dst, const void* src, uint32_t bytes, uint32_t mbar) {
    asm volatile("cp.async.bulk.shared::cluster.global.mbarrier::complete_tx::bytes [%0], [%1], %2, [%3];"
                 :: "r"(dst), "l"(src), "r"(bytes), "r"(mbar) : "memory");
}
__device__ __forceinline__ void ldsm4(uint32_t* r, uint32_t a) {
    asm volatile("ldmatrix.sync.aligned.m8n8.x4.shared.b16 {%0,%1,%2,%3}, [%4];"
                 : "=r"(r[0]), "=r"(r[1]), "=r"(r[2]), "=r"(r[3]) : "r"(a));
}
__device__ __forceinline__ void mma_s8(int* c, const uint32_t* a, uint32_t b0, uint32_t b1) {
    asm volatile("mma.sync.aligned.m16n8k32.row.col.s32.s8.s8.s32 "
                 "{%0,%1,%2,%3}, {%4,%5,%6,%7}, {%8,%9}, {%0,%1,%2,%3};"
                 : "+r"(c[0]), "+r"(c[1]), "+r"(c[2]), "+r"(c[3])
                 : "r"(a[0]), "r"(a[1]), "r"(a[2]), "r"(a[3]), "r"(b0), "r"(b1));
}

// ---------------- bucketing: fused histogram + scan -------------------------
__global__ void k_hist_scan(const int* __restrict__ idx) {
    const int t = threadIdx.x;
    int cnt[N_EXP];
    #pragma unroll
    for (int k = 0; k < N_EXP; ++k) cnt[k] = 0;
    for (int i = t; i < N_ROWS; i += 1024) {
        const int e = idx[i];
        #pragma unroll
        for (int k = 0; k < N_EXP; ++k) cnt[k] += (e == k);
    }
    #pragma unroll
    for (int k = 0; k < N_EXP; ++k)
        #pragma unroll
        for (int o = 16; o > 0; o >>= 1)
            cnt[k] += __shfl_xor_sync(0xffffffffu, cnt[k], o);
    __shared__ int acc[N_EXP];
    if (t < N_EXP) { acc[t] = 0; g_cur[t] = 0; }
    __syncthreads();
    if ((t & 31) == 0)
        #pragma unroll
        for (int k = 0; k < N_EXP; ++k) atomicAdd(&acc[k], cnt[k]);
    __syncthreads();
    if (t == 0) {
        int off = 0, tt = 0;
        for (int e = 0; e < N_EXP; ++e) {
            g_off[e] = off;
            const int c = acc[e];
            for (int r = 0; r < c; r += BM) { g_tile_e[tt] = e; g_tile_r[tt] = off + r; ++tt; }
            g_end[e] = off + c;
            off += (c + BM - 1) & ~(BM - 1);
        }
        g_off[N_EXP] = off;
        for (; tt < MAX_TILES; ++tt) g_tile_e[tt] = -1;
    }
}
// smem-aggregated scatter: one global atomicAdd per expert per block
__global__ void k_scatter(const int* __restrict__ idx) {
    __shared__ int loc[N_EXP], base[N_EXP];
    const int tid = threadIdx.x;
    if (tid < N_EXP) loc[tid] = 0;
    __syncthreads();
    const int i = blockIdx.x * 256 + tid;       // 64 * 256 == N_ROWS exactly
    const int e = idx[i];
    const int r = atomicAdd(&loc[e], 1);
    __syncthreads();
    if (tid < N_EXP) base[tid] = atomicAdd(&g_cur[tid], loc[tid]);
    __syncthreads();
    g_perm[g_off[e] + base[e] + r] = i;
}

// ---------------- fused int8 two-stream quantization (integer path) ---------
__device__ __forceinline__ float rowmax256(float4 v) {
    __shared__ float red[8];
    const int t = threadIdx.x;
    float m = fmaxf(fmaxf(fabsf(v.x), fabsf(v.y)), fmaxf(fabsf(v.z), fabsf(v.w)));
    #pragma unroll
    for (int o = 16; o > 0; o >>= 1) m = fmaxf(m, __shfl_xor_sync(0xffffffffu, m, o));
    if ((t & 31) == 0) red[t >> 5] = m;
    __syncthreads();
    if (t < 32) {
        float mm = (t < 8) ? red[t] : 0.f;
        #pragma unroll
        for (int o = 4; o > 0; o >>= 1) mm = fmaxf(mm, __shfl_xor_sync(0xffffffffu, mm, o));
        if (t == 0) red[0] = fmaxf(mm, 1e-30f);
    }
    __syncthreads();
    return red[0];
}
// full = rint(f * 16256/max)  ->  x0 = (full+64)>>7 in [-127,127],
// x1 = full - 128*x0 in [-64,63].  x ~= (x0 + x1/128) * max/127.
__device__ __forceinline__ void quant4i(float4 v, float q128, uint32_t& c0, uint32_t& c1) {
    float f[4] = {v.x, v.y, v.z, v.w};
    int x0[4], x1[4];
    #pragma unroll
    for (int i = 0; i < 4; ++i) {
        const int full = __float2int_rn(f[i] * q128);
        x0[i] = (full + 64) >> 7;
        x1[i] = full - (x0[i] << 7);
    }
    c0 = __byte_perm(__byte_perm(x0[0], x0[1], 0x0040),
                     __byte_perm(x0[2], x0[3], 0x0040), 0x5410);
    c1 = __byte_perm(__byte_perm(x1[0], x1[1], 0x0040),
                     __byte_perm(x1[2], x1[3], 0x0040), 0x5410);
}
// blocks [0, E*D_OUT): W rows; blocks [E*D_OUT, E*D_OUT+NPAD): x slots
__global__ void k_convert(const float* __restrict__ x, const float* __restrict__ W) {
    const int bb = blockIdx.x;
    const int t = threadIdx.x;
    if (bb < N_EXP * D_OUT) {
        const int r = bb;
        const int e = r >> 9, co = r & 511;
        float4 v = ((const float4*)(W + (size_t)r * D_IN))[t];
        const float maxv = rowmax256(v);
        uint32_t c0, c1;
        quant4i(v, 16256.f / maxv, c0, c1);
        const int ck = t >> 3;
        const int j  = (t & 7) * 4;
        const int js = j ^ ((co & 4) ? 16 : 0);
        const size_t base = ((size_t)(e * NCHUNK + ck) * D_OUT + co) * 32 + js;
        *(uint32_t*)(g_w0c + base) = c0;
        *(uint32_t*)(g_w1c + base) = c1;
        if (t == 0) g_invqw[r] = maxv * (1.f / 127.f);
    } else {
        const int p = bb - N_EXP * D_OUT;
        int e = 0;
        #pragma unroll
        for (int k = 1; k < N_EXP; ++k) e += (p >= g_off[k]);
        if (p >= g_end[e]) return;                 // pad slot: skip
        const int src = g_perm[p];
        float4 v = ((const float4*)(x + (size_t)src * D_IN))[t];
        const float maxv = rowmax256(v);
        uint32_t c0, c1;
        quant4i(v, 16256.f / maxv, c0, c1);
        const int ck = t >> 3;
        const int j  = (t & 7) * 4;
        const int js = j ^ ((p & 4) ? 16 : 0);
        const size_t base = ((size_t)ck * NPAD + p) * 32 + js;
        *(uint32_t*)(g_x0c + base) = c0;
        *(uint32_t*)(g_x1c + base) = c1;
        if (t == 0) g_invqx[p] = maxv * (1.f / 127.f);
    }
}

// ---------------- grouped int8 GEMM (bulk-copy pipeline, fixed grid) --------
__global__ void __launch_bounds__(NTHREADS, 1) k_gemm(const float* __restrict__ b,
                                                      float* __restrict__ y) {
    const int e = g_tile_e[blockIdx.x];
    if (e < 0) return;
    const int row0    = g_tile_r[blockIdx.x];
    const int row_end = g_end[e];
    const int n0      = blockIdx.y * BN;

    extern __shared__ char smem[];
    __shared__ uint64_t mbar[NSTAGE];
    const uint32_t sb = smem_u32(smem);

    const int tid  = threadIdx.x;
    const int lane = tid & 31;
    const int warp = tid >> 5;
    const int warp_m = warp >> 2;       // 0..3 (32 rows each)
    const int warp_n = warp & 3;        // 0..3 (32 cols each)

    if (tid == 0) {
        #pragma unroll
        for (int s = 0; s < NSTAGE; ++s) MBARRIER_INIT(smem_u32(&mbar[s]), 1);
    }
    __syncthreads();

    auto issue = [&](int s, int ck) {
        const uint32_t mb = smem_u32(&mbar[s]);
        MBARRIER_EXPECT_TX(mb, STG);
        const uint32_t st = sb + s * STG;
        bulk_g2s(st,         g_x0c + ((size_t)ck * NPAD + row0) * 32, 4096, mb);
        bulk_g2s(st + 4096,  g_x1c + ((size_t)ck * NPAD + row0) * 32, 4096, mb);
        bulk_g2s(st + 8192,  g_w0c + ((size_t)(e * NCHUNK + ck) * D_OUT + n0) * 32, 4096, mb);
        bulk_g2s(st + 12288, g_w1c + ((size_t)(e * NCHUNK + ck) * D_OUT + n0) * 32, 4096, mb);
    };
    if (tid == 0) { issue(0, 0); issue(1, 1); issue(2, 2); }

    int accA[2][4][4], accC[2][4][4];
    #pragma unroll
    for (int i = 0; i < 2; ++i)
        #pragma unroll
        for (int j = 0; j < 4; ++j)
            #pragma unroll
            for (int k = 0; k < 4; ++k) { accA[i][j][k] = 0; accC[i][j][k] = 0; }

    const uint32_t a_row  = warp_m * 32 + (lane & 15);
    const uint32_t a_koff = (lane >> 4) * 16;
    const uint32_t aswz   = (a_row & 4) ? 16u : 0u;
    const uint32_t b_row  = warp_n * 32 + (lane & 7) + ((lane >> 4) & 1) * 8;
    const uint32_t b_koff = ((lane >> 3) & 1) * 16;
    const uint32_t bswz   = (b_row & 4) ? 16u : 0u;

    for (int c = 0; c < NCHUNK; ++c) {
        const int s = c & (NSTAGE - 1);
        MBARRIER_WAIT_PARITY(smem_u32(&mbar[s]), (c >> 2) & 1);
        __syncthreads();                       // all reads of stage (c-1) done
        if (tid == 0 && c + 3 < NCHUNK) issue((c + 3) & (NSTAGE - 1), c + 3);

        const uint32_t st = sb + s * STG;
        uint32_t a0[2][4], a1[2][4], w0[2][4], w1[2][4];
        #pragma unroll
        for (int mt = 0; mt < 2; ++mt) {
            const uint32_t ad = st + (a_row + mt * 16) * 32 + (a_koff ^ aswz);
            ldsm4(a0[mt], ad);
            ldsm4(a1[mt], ad + 4096);
        }
        #pragma unroll
        for (int nt2 = 0; nt2 < 2; ++nt2) {
            const uint32_t bd = st + 8192 + (b_row + nt2 * 16) * 32 + (b_koff ^ bswz);
            ldsm4(w0[nt2], bd);
            ldsm4(w1[nt2], bd + 4096);
        }
        #pragma unroll
        for (int mt = 0; mt < 2; ++mt)
            #pragma unroll
            for (int nt = 0; nt < 4; ++nt) {
                const uint32_t* p0 = &w0[nt >> 1][(nt & 1) * 2];
                const uint32_t* p1 = &w1[nt >> 1][(nt & 1) * 2];
                mma_s8(accA[mt][nt], a0[mt], p0[0], p0[1]);   // X0*W0 -> main
                mma_s8(accC[mt][nt], a0[mt], p1[0], p1[1]);   // X0*W1 -> corr
                mma_s8(accC[mt][nt], a1[mt], p0[0], p0[1]);   // X1*W0 -> corr
            }
    }

    // epilogue: y = (accA + accC/128) * invqx[row]*invqw[col] + bias
    const float inv128 = 1.f / 128.f;
    const int ncol = n0 + warp_n * 32 + (lane & 3) * 2;
    float2 bias[4], fw[4];
    #pragma unroll
    for (int nt = 0; nt < 4; ++nt) {
        bias[nt] = *(const float2*)(b + (size_t)e * D_OUT + ncol + nt * 8);
        fw[nt]   = *(const float2*)(g_invqw + (size_t)e * D_OUT + ncol + nt * 8);
    }
    #pragma unroll
    for (int mt = 0; mt < 2; ++mt)
        #pragma unroll
        for (int half = 0; half < 2; ++half) {
            const int sr = row0 + warp_m * 32 + mt * 16 + (lane >> 2) + half * 8;
            if (sr < row_end) {
                const int g = g_perm[sr];
                const float fx = g_invqx[sr];
                float* yp = y + (size_t)g * D_OUT + ncol;
                #pragma unroll
                for (int nt = 0; nt < 4; ++nt) {
                    float v0 = (float)accA[mt][nt][half * 2 + 0]
                             + (float)accC[mt][nt][half * 2 + 0] * inv128;
                    float v1 = (float)accA[mt][nt][half * 2 + 1]
                             + (float)accC[mt][nt][half * 2 + 1] * inv128;
                    float2 v;
                    v.x = v0 * fx * fw[nt].x + bias[nt].x;
                    v.y = v1 * fx * fw[nt].y + bias[nt].y;
                    *(float2*)(yp + nt * 8) = v;
                }
            }
        }
}

// ---------------- entry -----------------------------------------------------
extern "C" void kernel_launch(void* const* d_in, const int* in_sizes, int n_in,
                              void* d_out, int out_size) {
    const float* x   = (const float*)d_in[0];
    const int*   idx = (const int*)  d_in[1];
    const float* W   = (const float*)d_in[2];
    const float* b   = (const float*)d_in[3];
    float*       y   = (float*)d_out;

    cudaFuncSetAttribute(k_gemm, cudaFuncAttributeMaxDynamicSharedMemorySize, SMEM_TOTAL);

    k_hist_scan<<<1, 1024>>>(idx);
    k_scatter<<<N_ROWS / 256, 256>>>(idx);
    k_convert<<<N_EXP * D_OUT + NPAD, 256>>>(x, W);

    dim3 grid(MAX_TILES, D_OUT / BN);
    k_gemm<<<grid, NTHREADS, SMEM_TOTAL>>>(b, y);
}

// round 14
// speedup vs baseline: 1.1446x; 1.1262x over previous
#include <cuda_runtime.h>
#include <cuda_bf16.h>
#include <cstdint>

// Problem constants
#define N_ROWS 16384
#define D_IN   1024
#define D_OUT  512
#define N_EXP  8
#define NPAD   (N_ROWS + N_EXP * 128)   // 17408: per-expert 128-padded row space

// GEMM tiling: 128x64 CTA tile, 8 warps of 32x32, 2 CTAs/SM
#define BM 128
#define BN 64
#define KC 32
#define NCHUNK (D_IN / KC)              // 32
#define NSTAGE 4
#define NTHREADS 256
#define MAX_TILES (N_ROWS / 128 + N_EXP) // 136

// SMEM stage: X0(4K) | X1(4K) | W0(2K) | W1(2K) = 12KB/stage
#define STG 12288
#define SMEM_TOTAL (NSTAGE * STG)       // 49152

// ---------------- device scratch ------------------------------------------
__device__ int g_cur[N_EXP];
__device__ int g_off[N_EXP + 1];
__device__ int g_end[N_EXP];
__device__ int g_perm[NPAD];
__device__ int g_tile_e[MAX_TILES];
__device__ int g_tile_r[MAX_TILES];
__device__ uint8_t g_x0c[(size_t)NCHUNK * NPAD * 32];
__device__ uint8_t g_x1c[(size_t)NCHUNK * NPAD * 32];
__device__ uint8_t g_w0c[(size_t)N_EXP * NCHUNK * D_OUT * 32];
__device__ uint8_t g_w1c[(size_t)N_EXP * NCHUNK * D_OUT * 32];
__device__ float   g_invqx[NPAD];
__device__ float   g_invqw[N_EXP * D_OUT];

// ---------------- PTX helpers ----------------------------------------------
__device__ __forceinline__ uint32_t smem_u32(const void* p) {
    uint32_t a;
    asm("{ .reg .u64 t; cvta.to.shared.u64 t, %1; cvt.u32.u64 %0, t; }" : "=r"(a) : "l"(p));
    return a;
}
#define MBARRIER_INIT(a, n) \
    asm volatile("mbarrier.init.shared.b64 [%0], %1;" :: "r"((uint32_t)(a)), "r"((uint32_t)(n)) : "memory")
#define MBARRIER_EXPECT_TX(a, tx) \
    asm volatile("mbarrier.arrive.expect_tx.shared.b64 _, [%0], %1;" :: "r"((uint32_t)(a)), "r"((uint32_t)(tx)) : "memory")
#define MBARRIER_WAIT_PARITY(a, ph) do { \
    uint32_t _m = (uint32_t)(a); uint32_t _p = (uint32_t)(ph); uint32_t _d; \
    asm volatile("{ .reg .pred p; mbarrier.try_wait.parity.acquire.cta.shared::cta.b64 p, [%1], %2; selp.b32 %0, 1, 0, p; }" \
        : "=r"(_d) : "r"(_m), "r"(_p) : "memory"); \
    if (!_d) { \
        asm volatile("{ .reg .pred P1; WL_%=: mbarrier.try_wait.parity.acquire.cta.shared::cta.b64 P1, [%0], %1, 0x989680; @P1 bra.uni WD_%=; bra.uni WL_%=; WD_%=: }" \
            :: "r"(_m), "r"(_p) : "memory"); \
    } } while (0)
__device__ __forceinline__ void bulk_g2s(uint32_t dst, const void* src, uint32_t bytes, uint32_t mbar) {
    asm volatile("cp.async.bulk.shared::cluster.global.mbarrier::complete_tx::bytes [%0], [%1], %2, [%3];"
                 :: "r"(dst), "l"(src), "r"(bytes), "r"(mbar) : "memory");
}
__device__ __forceinline__ void ldsm4(uint32_t* r, uint32_t a) {
    asm volatile("ldmatrix.sync.aligned.m8n8.x4.shared.b16 {%0,%1,%2,%3}, [%4];"
                 : "=r"(r[0]), "=r"(r[1]), "=r"(r[2]), "=r"(r[3]) : "r"(a));
}
__device__ __forceinline__ void mma_s8(int* c, const uint32_t* a, uint32_t b0, uint32_t b1) {
    asm volatile("mma.sync.aligned.m16n8k32.row.col.s32.s8.s8.s32 "
                 "{%0,%1,%2,%3}, {%4,%5,%6,%7}, {%8,%9}, {%0,%1,%2,%3};"
                 : "+r"(c[0]), "+r"(c[1]), "+r"(c[2]), "+r"(c[3])
                 : "r"(a[0]), "r"(a[1]), "r"(a[2]), "r"(a[3]), "r"(b0), "r"(b1));
}

// ---------------- bucketing: fused histogram + scan -------------------------
__global__ void k_hist_scan(const int* __restrict__ idx) {
    const int t = threadIdx.x;
    int cnt[N_EXP];
    #pragma unroll
    for (int k = 0; k < N_EXP; ++k) cnt[k] = 0;
    for (int i = t; i < N_ROWS; i += 1024) {
        const int e = idx[i];
        #pragma unroll
        for (int k = 0; k < N_EXP; ++k) cnt[k] += (e == k);
    }
    #pragma unroll
    for (int k = 0; k < N_EXP; ++k)
        #pragma unroll
        for (int o = 16; o > 0; o >>= 1)
            cnt[k] += __shfl_xor_sync(0xffffffffu, cnt[k], o);
    __shared__ int acc[N_EXP];
    if (t < N_EXP) { acc[t] = 0; g_cur[t] = 0; }
    __syncthreads();
    if ((t & 31) == 0)
        #pragma unroll
        for (int k = 0; k < N_EXP; ++k) atomicAdd(&acc[k], cnt[k]);
    __syncthreads();
    if (t == 0) {
        int off = 0, tt = 0;
        for (int e = 0; e < N_EXP; ++e) {
            g_off[e] = off;
            const int c = acc[e];
            for (int r = 0; r < c; r += 128) { g_tile_e[tt] = e; g_tile_r[tt] = off + r; ++tt; }
            g_end[e] = off + c;
            off += (c + 127) & ~127;
        }
        g_off[N_EXP] = off;
        for (; tt < MAX_TILES; ++tt) g_tile_e[tt] = -1;
    }
}
__global__ void k_scatter(const int* __restrict__ idx) {
    __shared__ int loc[N_EXP], base[N_EXP];
    const int tid = threadIdx.x;
    if (tid < N_EXP) loc[tid] = 0;
    __syncthreads();
    const int i = blockIdx.x * 256 + tid;
    const int e = idx[i];
    const int r = atomicAdd(&loc[e], 1);
    __syncthreads();
    if (tid < N_EXP) base[tid] = atomicAdd(&g_cur[tid], loc[tid]);
    __syncthreads();
    g_perm[g_off[e] + base[e] + r] = i;
}

// ---------------- fused int8 two-stream quantization (integer path) ---------
__device__ __forceinline__ float rowmax256(float4 v) {
    __shared__ float red[8];
    const int t = threadIdx.x;
    float m = fmaxf(fmaxf(fabsf(v.x), fabsf(v.y)), fmaxf(fabsf(v.z), fabsf(v.w)));
    #pragma unroll
    for (int o = 16; o > 0; o >>= 1) m = fmaxf(m, __shfl_xor_sync(0xffffffffu, m, o));
    if ((t & 31) == 0) red[t >> 5] = m;
    __syncthreads();
    if (t < 32) {
        float mm = (t < 8) ? red[t] : 0.f;
        #pragma unroll
        for (int o = 4; o > 0; o >>= 1) mm = fmaxf(mm, __shfl_xor_sync(0xffffffffu, mm, o));
        if (t == 0) red[0] = fmaxf(mm, 1e-30f);
    }
    __syncthreads();
    return red[0];
}
__device__ __forceinline__ void quant4i(float4 v, float q128, uint32_t& c0, uint32_t& c1) {
    float f[4] = {v.x, v.y, v.z, v.w};
    int x0[4], x1[4];
    #pragma unroll
    for (int i = 0; i < 4; ++i) {
        const int full = __float2int_rn(f[i] * q128);
        x0[i] = (full + 64) >> 7;
        x1[i] = full - (x0[i] << 7);
    }
    c0 = __byte_perm(__byte_perm(x0[0], x0[1], 0x0040),
                     __byte_perm(x0[2], x0[3], 0x0040), 0x5410);
    c1 = __byte_perm(__byte_perm(x1[0], x1[1], 0x0040),
                     __byte_perm(x1[2], x1[3], 0x0040), 0x5410);
}
__global__ void k_convert(const float* __restrict__ x, const float* __restrict__ W) {
    const int bb = blockIdx.x;
    const int t = threadIdx.x;
    if (bb < N_EXP * D_OUT) {
        const int r = bb;
        const int e = r >> 9, co = r & 511;
        float4 v = ((const float4*)(W + (size_t)r * D_IN))[t];
        const float maxv = rowmax256(v);
        uint32_t c0, c1;
        quant4i(v, 16256.f / maxv, c0, c1);
        const int ck = t >> 3;
        const int j  = (t & 7) * 4;
        const int js = j ^ ((co & 4) ? 16 : 0);
        const size_t base = ((size_t)(e * NCHUNK + ck) * D_OUT + co) * 32 + js;
        *(uint32_t*)(g_w0c + base) = c0;
        *(uint32_t*)(g_w1c + base) = c1;
        if (t == 0) g_invqw[r] = maxv * (1.f / 127.f);
    } else {
        const int p = bb - N_EXP * D_OUT;
        int e = 0;
        #pragma unroll
        for (int k = 1; k < N_EXP; ++k) e += (p >= g_off[k]);
        if (p >= g_end[e]) return;
        const int src = g_perm[p];
        float4 v = ((const float4*)(x + (size_t)src * D_IN))[t];
        const float maxv = rowmax256(v);
        uint32_t c0, c1;
        quant4i(v, 16256.f / maxv, c0, c1);
        const int ck = t >> 3;
        const int j  = (t & 7) * 4;
        const int js = j ^ ((p & 4) ? 16 : 0);
        const size_t base = ((size_t)ck * NPAD + p) * 32 + js;
        *(uint32_t*)(g_x0c + base) = c0;
        *(uint32_t*)(g_x1c + base) = c1;
        if (t == 0) g_invqx[p] = maxv * (1.f / 127.f);
    }
}

// ---------------- grouped int8 GEMM: 128x64 tiles, 2 CTAs/SM ----------------
__global__ void __launch_bounds__(NTHREADS, 2) k_gemm(const float* __restrict__ b,
                                                      float* __restrict__ y) {
    const int e = g_tile_e[blockIdx.x];
    if (e < 0) return;
    const int row0    = g_tile_r[blockIdx.x];
    const int row_end = g_end[e];
    const int n0      = blockIdx.y * BN;

    extern __shared__ char smem[];
    __shared__ uint64_t mbar[NSTAGE];
    const uint32_t sb = smem_u32(smem);

    const int tid  = threadIdx.x;
    const int lane = tid & 31;
    const int warp = tid >> 5;
    const int warp_m = warp >> 1;       // 0..3 (32 rows each)
    const int warp_n = warp & 1;        // 0..1 (32 cols each)

    if (tid == 0) {
        #pragma unroll
        for (int s = 0; s < NSTAGE; ++s) MBARRIER_INIT(smem_u32(&mbar[s]), 1);
    }
    __syncthreads();

    auto issue = [&](int s, int ck) {
        const uint32_t mb = smem_u32(&mbar[s]);
        MBARRIER_EXPECT_TX(mb, STG);
        const uint32_t st = sb + s * STG;
        bulk_g2s(st,         g_x0c + ((size_t)ck * NPAD + row0) * 32, 4096, mb);
        bulk_g2s(st + 4096,  g_x1c + ((size_t)ck * NPAD + row0) * 32, 4096, mb);
        bulk_g2s(st + 8192,  g_w0c + ((size_t)(e * NCHUNK + ck) * D_OUT + n0) * 32, 2048, mb);
        bulk_g2s(st + 10240, g_w1c + ((size_t)(e * NCHUNK + ck) * D_OUT + n0) * 32, 2048, mb);
    };
    if (tid == 0) { issue(0, 0); issue(1, 1); issue(2, 2); }

    int accA[2][4][4], accC[2][4][4];
    #pragma unroll
    for (int i = 0; i < 2; ++i)
        #pragma unroll
        for (int j = 0; j < 4; ++j)
            #pragma unroll
            for (int k = 0; k < 4; ++k) { accA[i][j][k] = 0; accC[i][j][k] = 0; }

    const uint32_t a_row  = warp_m * 32 + (lane & 15);
    const uint32_t a_koff = (lane >> 4) * 16;
    const uint32_t aswz   = (a_row & 4) ? 16u : 0u;
    const uint32_t b_row  = warp_n * 32 + (lane & 7) + ((lane >> 4) & 1) * 8;
    const uint32_t b_koff = ((lane >> 3) & 1) * 16;
    const uint32_t bswz   = (b_row & 4) ? 16u : 0u;

    for (int c = 0; c < NCHUNK; ++c) {
        const int s = c & (NSTAGE - 1);
        MBARRIER_WAIT_PARITY(smem_u32(&mbar[s]), (c >> 2) & 1);
        __syncthreads();
        if (tid == 0 && c + 3 < NCHUNK) issue((c + 3) & (NSTAGE - 1), c + 3);

        const uint32_t st = sb + s * STG;
        uint32_t a0[2][4], a1[2][4], w0[2][4], w1[2][4];
        #pragma unroll
        for (int mt = 0; mt < 2; ++mt) {
            const uint32_t ad = st + (a_row + mt * 16) * 32 + (a_koff ^ aswz);
            ldsm4(a0[mt], ad);
            ldsm4(a1[mt], ad + 4096);
        }
        #pragma unroll
        for (int nt2 = 0; nt2 < 2; ++nt2) {
            const uint32_t bd = st + 8192 + (b_row + nt2 * 16) * 32 + (b_koff ^ bswz);
            ldsm4(w0[nt2], bd);
            ldsm4(w1[nt2], bd + 2048);
        }
        #pragma unroll
        for (int mt = 0; mt < 2; ++mt)
            #pragma unroll
            for (int nt = 0; nt < 4; ++nt) {
                const uint32_t* p0 = &w0[nt >> 1][(nt & 1) * 2];
                const uint32_t* p1 = &w1[nt >> 1][(nt & 1) * 2];
                mma_s8(accA[mt][nt], a0[mt], p0[0], p0[1]);   // X0*W0
                mma_s8(accC[mt][nt], a0[mt], p1[0], p1[1]);   // X0*W1
                mma_s8(accC[mt][nt], a1[mt], p0[0], p0[1]);   // X1*W0
            }
    }

    // epilogue: y = (accA + accC/128) * invqx[row]*invqw[col] + bias
    const float inv128 = 1.f / 128.f;
    const int ncol = n0 + warp_n * 32 + (lane & 3) * 2;
    float2 bias[4], fw[4];
    #pragma unroll
    for (int nt = 0; nt < 4; ++nt) {
        bias[nt] = *(const float2*)(b + (size_t)e * D_OUT + ncol + nt * 8);
        fw[nt]   = *(const float2*)(g_invqw + (size_t)e * D_OUT + ncol + nt * 8);
    }
    #pragma unroll
    for (int mt = 0; mt < 2; ++mt)
        #pragma unroll
        for (int half = 0; half < 2; ++half) {
            const int sr = row0 + warp_m * 32 + mt * 16 + (lane >> 2) + half * 8;
            if (sr < row_end) {
                const int g = g_perm[sr];
                const float fx = g_invqx[sr];
                float* yp = y + (size_t)g * D_OUT + ncol;
                #pragma unroll
                for (int nt = 0; nt < 4; ++nt) {
                    float v0 = (float)accA[mt][nt][half * 2 + 0]
                             + (float)accC[mt][nt][half * 2 + 0] * inv128;
                    float v1 = (float)accA[mt][nt][half * 2 + 1]
                             + (float)accC[mt][nt][half * 2 + 1] * inv128;
                    float2 v;
                    v.x = v0 * fx * fw[nt].x + bias[nt].x;
                    v.y = v1 * fx * fw[nt].y + bias[nt].y;
                    *(float2*)(yp + nt * 8) = v;
                }
            }
        }
}

// ---------------- entry -----------------------------------------------------
extern "C" void kernel_launch(void* const* d_in, const int* in_sizes, int n_in,
                              void* d_out, int out_size) {
    const float* x   = (const float*)d_in[0];
    const int*   idx = (const int*)  d_in[1];
    const float* W   = (const float*)d_in[2];
    const float* b   = (const float*)d_in[3];
    float*       y   = (float*)d_out;

    cudaFuncSetAttribute(k_gemm, cudaFuncAttributeMaxDynamicSharedMemorySize, SMEM_TOTAL);

    k_hist_scan<<<1, 1024>>>(idx);
    k_scatter<<<N_ROWS / 256, 256>>>(idx);
    k_convert<<<N_EXP * D_OUT + NPAD, 256>>>(x, W);

    dim3 grid(MAX_TILES, D_OUT / BN);
    k_gemm<<<grid, NTHREADS, SMEM_TOTAL>>>(b, y);
}